// round 10
// baseline (speedup 1.0000x reference)
#include <cuda_runtime.h>
#include <cstdint>

#define NN 100000
#define EMAX 1600000
#define EPS 1e-5f
#define SCAN_CHUNK 256
#define NBLK ((NN + SCAN_CHUNK - 1) / SCAN_CHUNK)   // 391

// ---- scratch (static __device__ globals; no allocation at runtime) ----
__device__ __align__(16) float g_bufA[(size_t)NN * 128];
__device__ __align__(16) float g_bufB[(size_t)NN * 128];
__device__ float g_dinv[NN];
__device__ int   g_deg[NN];
__device__ int   g_off[NN];
__device__ int   g_cur[NN];
__device__ __align__(8) int2 g_csr[EMAX];   // {src, bitcast(norm)}
__device__ int   g_bsum[512];
__device__ int   g_boff[512];
__device__ int   g_is64;

// ---------------------------------------------------------------------
// Fused: zero g_deg + detect int64 vs int32 edge_index (block 0).
__global__ void init_detect_kernel(const void* ei_raw, int E, int n_nodes) {
    int i = blockIdx.x * blockDim.x + threadIdx.x;
    if (i < n_nodes) g_deg[i] = 0;
    if (blockIdx.x == 0) {
        if (threadIdx.x == 0) g_is64 = 1;
        __syncthreads();
        const long long* e64 = (const long long*)ei_raw;
        int cnt = (2 * E < 1024) ? 2 * E : 1024;
        for (int k = threadIdx.x; k < cnt; k += blockDim.x) {
            long long v = e64[k];
            if (v < 0 || v >= n_nodes) atomicExch(&g_is64, 0);
        }
    }
}

// degree count: decode dst on the fly, 4 edges per thread
__global__ void count_deg_kernel(const void* ei_raw, int E) {
    int t = blockIdx.x * blockDim.x + threadIdx.x;
    int e0 = t * 4;
    if (e0 >= E) return;
    int cnt = (E - e0 < 4) ? (E - e0) : 4;
    if (g_is64) {
        const long long* ei = (const long long*)ei_raw;
        for (int i = 0; i < cnt; i++)
            atomicAdd(&g_deg[(int)ei[(size_t)E + e0 + i]], 1);
    } else {
        const int* ei = (const int*)ei_raw;
        if (cnt == 4) {
            int4 dv = __ldg(&reinterpret_cast<const int4*>(ei + E)[t]);
            atomicAdd(&g_deg[dv.x], 1);
            atomicAdd(&g_deg[dv.y], 1);
            atomicAdd(&g_deg[dv.z], 1);
            atomicAdd(&g_deg[dv.w], 1);
        } else {
            for (int i = 0; i < cnt; i++)
                atomicAdd(&g_deg[ei[(size_t)E + e0 + i]], 1);
        }
    }
}

// ---- 3-kernel exclusive scan of g_deg -> g_off -----------------------
__global__ void scan_block_sum_kernel(int n) {
    __shared__ int sh[SCAN_CHUNK];
    int i = blockIdx.x * SCAN_CHUNK + threadIdx.x;
    sh[threadIdx.x] = (i < n) ? g_deg[i] : 0;
    __syncthreads();
    for (int s = SCAN_CHUNK / 2; s; s >>= 1) {
        if (threadIdx.x < s) sh[threadIdx.x] += sh[threadIdx.x + s];
        __syncthreads();
    }
    if (threadIdx.x == 0) g_bsum[blockIdx.x] = sh[0];
}

__global__ void scan_boff_kernel(int nb) {
    __shared__ int sh[512];
    int v = (threadIdx.x < nb) ? g_bsum[threadIdx.x] : 0;
    sh[threadIdx.x] = v;
    __syncthreads();
    for (int o = 1; o < 512; o <<= 1) {
        int t = (threadIdx.x >= o) ? sh[threadIdx.x - o] : 0;
        __syncthreads();
        sh[threadIdx.x] += t;
        __syncthreads();
    }
    if (threadIdx.x < nb) g_boff[threadIdx.x] = sh[threadIdx.x] - v;
}

__global__ void scan_final_kernel(int n) {
    __shared__ int sh[SCAN_CHUNK];
    int i = blockIdx.x * SCAN_CHUNK + threadIdx.x;
    int v = (i < n) ? g_deg[i] : 0;
    sh[threadIdx.x] = v;
    __syncthreads();
    for (int o = 1; o < SCAN_CHUNK; o <<= 1) {
        int t = (threadIdx.x >= o) ? sh[threadIdx.x - o] : 0;
        __syncthreads();
        sh[threadIdx.x] += t;
        __syncthreads();
    }
    if (i < n) {
        int off = g_boff[blockIdx.x] + sh[threadIdx.x] - v;
        g_off[i] = off;
        g_cur[i] = off;
        g_dinv[i] = rsqrtf((float)v + 1.0f);   // fused dinv
    }
}

// CSR fill: decode edges again (no staging arrays)
__global__ void fill_csr_kernel(const void* ei_raw, int E) {
    int e = blockIdx.x * blockDim.x + threadIdx.x;
    if (e >= E) return;
    int s, d;
    if (g_is64) {
        const long long* ei = (const long long*)ei_raw;
        s = (int)ei[e];
        d = (int)ei[(size_t)E + e];
    } else {
        const int* ei = (const int*)ei_raw;
        s = __ldg(&ei[e]);
        d = __ldg(&ei[(size_t)E + e]);
    }
    int pos = atomicAdd(&g_cur[d], 1);
    float nrm = g_dinv[s] * g_dinv[d];
    g_csr[pos] = make_int2(s, __float_as_int(nrm));
}

// ---- packed-f32x2 helpers --------------------------------------------
__device__ __forceinline__ unsigned long long pkdup(float v) {
    unsigned long long r;
    asm("mov.b64 %0, {%1, %1};" : "=l"(r) : "f"(v));
    return r;
}
__device__ __forceinline__ void fma2(unsigned long long& acc,
                                     unsigned long long a,
                                     unsigned long long b) {
    asm("fma.rn.f32x2 %0, %1, %2, %0;" : "+l"(acc) : "l"(a), "l"(b));
}
__device__ __forceinline__ float2 unpk(unsigned long long v) {
    float lo, hi;
    asm("mov.b64 {%0, %1}, %2;" : "=f"(lo), "=f"(hi) : "l"(v));
    return make_float2(lo, hi);
}

// ---- software-pipelined CSR gather-accumulate (chunk 4, prefetch) ----
// Preserves sequential FP accumulation order.
__device__ __forceinline__ void agg_loop(const float4* __restrict__ h4,
                                         int off, int deg, int G, int c,
                                         float4& acc) {
    const int2* cp = g_csr + off;
    int nf = deg & ~3;
    int2 e0, e1, e2, e3;
    if (nf) {
        e0 = __ldg(cp + 0);
        e1 = __ldg(cp + 1);
        e2 = __ldg(cp + 2);
        e3 = __ldg(cp + 3);
    }
    for (int j = 0; j < nf; j += 4) {
        int2 p0 = make_int2(0, 0), p1 = p0, p2 = p0, p3 = p0;
        if (j + 4 < nf) {
            p0 = __ldg(cp + j + 4);
            p1 = __ldg(cp + j + 5);
            p2 = __ldg(cp + j + 6);
            p3 = __ldg(cp + j + 7);
        }
        float4 v0 = __ldg(&h4[(size_t)e0.x * G + c]);
        float4 v1 = __ldg(&h4[(size_t)e1.x * G + c]);
        float4 v2 = __ldg(&h4[(size_t)e2.x * G + c]);
        float4 v3 = __ldg(&h4[(size_t)e3.x * G + c]);
        float w0 = __int_as_float(e0.y);
        float w1 = __int_as_float(e1.y);
        float w2 = __int_as_float(e2.y);
        float w3 = __int_as_float(e3.y);
        acc.x += v0.x * w0; acc.y += v0.y * w0; acc.z += v0.z * w0; acc.w += v0.w * w0;
        acc.x += v1.x * w1; acc.y += v1.y * w1; acc.z += v1.z * w1; acc.w += v1.w * w1;
        acc.x += v2.x * w2; acc.y += v2.y * w2; acc.z += v2.z * w2; acc.w += v2.w * w2;
        acc.x += v3.x * w3; acc.y += v3.y * w3; acc.z += v3.z * w3; acc.w += v3.w * w3;
        e0 = p0; e1 = p1; e2 = p2; e3 = p3;
    }
    for (int j = nf; j < deg; j++) {
        int2 sn = __ldg(cp + j);
        float w = __int_as_float(sn.y);
        float4 v = __ldg(&h4[(size_t)sn.x * G + c]);
        acc.x += v.x * w; acc.y += v.y * w; acc.z += v.z * w; acc.w += v.w * w;
    }
}

// ---- GEMM: C[N,Fo] = H[N,Fi] @ W[Fi,Fo] (+bias), f32x2 over fo-pairs -
template <int Fi, int Fo, int NPT>
__global__ void gemm_f32x2_kernel(const float* __restrict__ H,
                                  const float* __restrict__ W,
                                  const float* __restrict__ bias,
                                  float* __restrict__ C, int N) {
    constexpr int F2 = Fo / 2;
    constexpr int NR = 256 / F2;
    __shared__ unsigned long long Ws[Fi * F2];   // Ws[k*F2 + f2]
    const unsigned long long* Wu = reinterpret_cast<const unsigned long long*>(W);
    for (int i = threadIdx.x; i < Fi * F2; i += 256) Ws[i] = Wu[i];
    __syncthreads();

    int f2 = threadIdx.x % F2;
    int nr = threadIdx.x / F2;
    int n0 = blockIdx.x * (NR * NPT) + nr * NPT;

    unsigned long long acc2[NPT];
#pragma unroll
    for (int r = 0; r < NPT; r++) acc2[r] = 0ull;

    const float4* H4 = reinterpret_cast<const float4*>(H);
#pragma unroll 2
    for (int k4 = 0; k4 < Fi / 4; k4++) {
        unsigned long long w0 = Ws[(k4 * 4 + 0) * F2 + f2];
        unsigned long long w1 = Ws[(k4 * 4 + 1) * F2 + f2];
        unsigned long long w2 = Ws[(k4 * 4 + 2) * F2 + f2];
        unsigned long long w3 = Ws[(k4 * 4 + 3) * F2 + f2];
#pragma unroll
        for (int r = 0; r < NPT; r++) {
            int n = n0 + r;
            if (n < N) {
                float4 h = __ldg(&H4[(size_t)n * (Fi / 4) + k4]);
                fma2(acc2[r], pkdup(h.x), w0);
                fma2(acc2[r], pkdup(h.y), w1);
                fma2(acc2[r], pkdup(h.z), w2);
                fma2(acc2[r], pkdup(h.w), w3);
            }
        }
    }
    float2 bb = bias ? reinterpret_cast<const float2*>(bias)[f2]
                     : make_float2(0.0f, 0.0f);
#pragma unroll
    for (int r = 0; r < NPT; r++) {
        int n = n0 + r;
        if (n < N) {
            float2 v = unpk(acc2[r]);
            reinterpret_cast<float2*>(C)[(size_t)n * F2 + f2] =
                make_float2(v.x + bb.x, v.y + bb.y);
        }
    }
}

// ---- GEMM + bias + LayerNorm + ELU fused (layer 2: 64 -> 128) --------
template <int Fi, int Fo, int NPT>
__global__ void gemm_ln_elu_kernel(const float* __restrict__ H,
                                   const float* __restrict__ W,
                                   const float* __restrict__ bias,
                                   const float* __restrict__ gam,
                                   const float* __restrict__ bet,
                                   float* __restrict__ C, int N) {
    constexpr int F2 = Fo / 2;        // 64
    constexpr int NR = 256 / F2;      // 4 row groups
    __shared__ unsigned long long Ws[Fi * F2];
    __shared__ float2 red[NR][2][NPT];   // (sum, sq) partials per warp half
    const unsigned long long* Wu = reinterpret_cast<const unsigned long long*>(W);
    for (int i = threadIdx.x; i < Fi * F2; i += 256) Ws[i] = Wu[i];
    __syncthreads();

    int f2 = threadIdx.x % F2;
    int nr = threadIdx.x / F2;
    int half = (f2 >> 5);             // which warp of the row group
    int n0 = blockIdx.x * (NR * NPT) + nr * NPT;

    unsigned long long acc2[NPT];
#pragma unroll
    for (int r = 0; r < NPT; r++) acc2[r] = 0ull;

    const float4* H4 = reinterpret_cast<const float4*>(H);
#pragma unroll 2
    for (int k4 = 0; k4 < Fi / 4; k4++) {
        unsigned long long w0 = Ws[(k4 * 4 + 0) * F2 + f2];
        unsigned long long w1 = Ws[(k4 * 4 + 1) * F2 + f2];
        unsigned long long w2 = Ws[(k4 * 4 + 2) * F2 + f2];
        unsigned long long w3 = Ws[(k4 * 4 + 3) * F2 + f2];
#pragma unroll
        for (int r = 0; r < NPT; r++) {
            int n = n0 + r;
            if (n < N) {
                float4 h = __ldg(&H4[(size_t)n * (Fi / 4) + k4]);
                fma2(acc2[r], pkdup(h.x), w0);
                fma2(acc2[r], pkdup(h.y), w1);
                fma2(acc2[r], pkdup(h.z), w2);
                fma2(acc2[r], pkdup(h.w), w3);
            }
        }
    }

    float2 bb = reinterpret_cast<const float2*>(bias)[f2];
    float2 vals[NPT];
#pragma unroll
    for (int r = 0; r < NPT; r++) {
        float2 v = unpk(acc2[r]);
        vals[r] = make_float2(v.x + bb.x, v.y + bb.y);
        float s = vals[r].x + vals[r].y;
        float q = vals[r].x * vals[r].x + vals[r].y * vals[r].y;
#pragma unroll
        for (int o = 16; o; o >>= 1) {
            s += __shfl_xor_sync(0xffffffffu, s, o);
            q += __shfl_xor_sync(0xffffffffu, q, o);
        }
        if ((threadIdx.x & 31) == 0) red[nr][half][r] = make_float2(s, q);
    }
    __syncthreads();

    float2 gg = reinterpret_cast<const float2*>(gam)[f2];
    float2 be = reinterpret_cast<const float2*>(bet)[f2];
#pragma unroll
    for (int r = 0; r < NPT; r++) {
        int n = n0 + r;
        if (n >= N) continue;
        float2 p0 = red[nr][0][r];
        float2 p1 = red[nr][1][r];
        float mean = (p0.x + p1.x) * (1.0f / Fo);
        float var  = (p0.y + p1.y) * (1.0f / Fo) - mean * mean;
        float inv  = rsqrtf(var + EPS);
        float yx = (vals[r].x - mean) * inv * gg.x + be.x;
        float yy = (vals[r].y - mean) * inv * gg.y + be.y;
        yx = (yx > 0.0f) ? yx : expm1f(yx);
        yy = (yy > 0.0f) ? yy : expm1f(yy);
        reinterpret_cast<float2*>(C)[(size_t)n * F2 + f2] = make_float2(yx, yy);
    }
}

// ---- plain CSR aggregation (self-loop, no bias/LN): out = A_hat @ h --
template <int F>
__global__ void agg_kernel(const float* __restrict__ h,
                           float* __restrict__ out, int N) {
    constexpr int G = F / 4;
    int gid = (int)((blockIdx.x * blockDim.x + threadIdx.x) / G);
    int c = threadIdx.x % G;
    if (gid >= N) return;

    const float4* h4 = reinterpret_cast<const float4*>(h);
    float di = g_dinv[gid];
    float sl = di * di;
    float4 a = __ldg(&h4[(size_t)gid * G + c]);
    float4 acc = make_float4(a.x * sl, a.y * sl, a.z * sl, a.w * sl);

    agg_loop(h4, g_off[gid], g_deg[gid], G, c, acc);

    reinterpret_cast<float4*>(out)[(size_t)gid * G + c] = acc;
}

// ---- fused CSR aggregation + self-loop + bias + LayerNorm + ELU ------
template <int F>
__global__ void agg_ln_elu_kernel(const float* __restrict__ xw,
                                  const float* __restrict__ bias,
                                  const float* __restrict__ gam,
                                  const float* __restrict__ bet,
                                  float* __restrict__ out, int N) {
    constexpr int G = F / 4;
    int gid = (int)((blockIdx.x * blockDim.x + threadIdx.x) / G);
    int c = threadIdx.x % G;
    if (gid >= N) return;

    const float4* xw4 = reinterpret_cast<const float4*>(xw);
    float di = g_dinv[gid];
    float sl = di * di;
    float4 a = __ldg(&xw4[(size_t)gid * G + c]);
    float4 acc = make_float4(a.x * sl, a.y * sl, a.z * sl, a.w * sl);

    agg_loop(xw4, g_off[gid], g_deg[gid], G, c, acc);

    float4 bb = __ldg(&reinterpret_cast<const float4*>(bias)[c]);
    acc.x += bb.x; acc.y += bb.y; acc.z += bb.z; acc.w += bb.w;

    float sum = acc.x + acc.y + acc.z + acc.w;
    float sq  = acc.x * acc.x + acc.y * acc.y + acc.z * acc.z + acc.w * acc.w;
#pragma unroll
    for (int o = G / 2; o; o >>= 1) {
        sum += __shfl_xor_sync(0xffffffffu, sum, o);
        sq  += __shfl_xor_sync(0xffffffffu, sq, o);
    }
    float mean = sum * (1.0f / F);
    float var  = sq * (1.0f / F) - mean * mean;
    float inv  = rsqrtf(var + EPS);

    float4 gg = __ldg(&reinterpret_cast<const float4*>(gam)[c]);
    float4 be = __ldg(&reinterpret_cast<const float4*>(bet)[c]);
    float4 y;
    y.x = (acc.x - mean) * inv * gg.x + be.x;
    y.y = (acc.y - mean) * inv * gg.y + be.y;
    y.z = (acc.z - mean) * inv * gg.z + be.z;
    y.w = (acc.w - mean) * inv * gg.w + be.w;
    y.x = (y.x > 0.0f) ? y.x : expm1f(y.x);
    y.y = (y.y > 0.0f) ? y.y : expm1f(y.y);
    y.z = (y.z > 0.0f) ? y.z : expm1f(y.z);
    y.w = (y.w > 0.0f) ? y.w : expm1f(y.w);
    reinterpret_cast<float4*>(out)[(size_t)gid * G + c] = y;
}

// ---- layer 3 + head fully fused:
// agg(64) + b3 + LN + ELU + lin(64->32) + LN + ELU + lin(32->32) -> out
__global__ void agg_ln_elu_head_kernel(const float* __restrict__ xw,
                                       const float* __restrict__ bias,
                                       const float* __restrict__ gam,
                                       const float* __restrict__ bet,
                                       const float* __restrict__ lw1,
                                       const float* __restrict__ lb1,
                                       const float* __restrict__ g4,
                                       const float* __restrict__ be4,
                                       const float* __restrict__ lw2,
                                       const float* __restrict__ lb2,
                                       float* __restrict__ out, int N) {
    constexpr int G = 16;             // threads per node (F=64)
    constexpr int NODES = 256 / G;    // 16 nodes per block
    __shared__ float s_w1[64 * 32];
    __shared__ float s_w2[32 * 32];
    __shared__ float s_b1[32], s_g4[32], s_be4[32], s_b2[32];
    __shared__ float h_sm[NODES][64];
    __shared__ float t_sm[NODES][32];

    for (int i = threadIdx.x; i < 64 * 32; i += 256) s_w1[i] = lw1[i];
    for (int i = threadIdx.x; i < 32 * 32; i += 256) s_w2[i] = lw2[i];
    if (threadIdx.x < 32) {
        s_b1[threadIdx.x]  = lb1[threadIdx.x];
        s_g4[threadIdx.x]  = g4[threadIdx.x];
        s_be4[threadIdx.x] = be4[threadIdx.x];
        s_b2[threadIdx.x]  = lb2[threadIdx.x];
    }
    __syncthreads();

    int node = threadIdx.x / G;       // node slot within block
    int c    = threadIdx.x % G;
    int gid  = blockIdx.x * NODES + node;
    bool active = (gid < N);

    float4 y = make_float4(0.0f, 0.0f, 0.0f, 0.0f);
    if (active) {
        const float4* xw4 = reinterpret_cast<const float4*>(xw);
        float di = g_dinv[gid];
        float sl = di * di;
        float4 a = __ldg(&xw4[(size_t)gid * G + c]);
        float4 acc = make_float4(a.x * sl, a.y * sl, a.z * sl, a.w * sl);

        agg_loop(xw4, g_off[gid], g_deg[gid], G, c, acc);

        float4 bb = __ldg(&reinterpret_cast<const float4*>(bias)[c]);
        acc.x += bb.x; acc.y += bb.y; acc.z += bb.z; acc.w += bb.w;

        float sum = acc.x + acc.y + acc.z + acc.w;
        float sq  = acc.x * acc.x + acc.y * acc.y + acc.z * acc.z + acc.w * acc.w;
#pragma unroll
        for (int o = 8; o; o >>= 1) {
            sum += __shfl_xor_sync(0xffffffffu, sum, o, 16);
            sq  += __shfl_xor_sync(0xffffffffu, sq, o, 16);
        }
        float mean = sum * (1.0f / 64.0f);
        float var  = sq * (1.0f / 64.0f) - mean * mean;
        float inv  = rsqrtf(var + EPS);

        float4 gg = __ldg(&reinterpret_cast<const float4*>(gam)[c]);
        float4 be = __ldg(&reinterpret_cast<const float4*>(bet)[c]);
        y.x = (acc.x - mean) * inv * gg.x + be.x;
        y.y = (acc.y - mean) * inv * gg.y + be.y;
        y.z = (acc.z - mean) * inv * gg.z + be.z;
        y.w = (acc.w - mean) * inv * gg.w + be.w;
        y.x = (y.x > 0.0f) ? y.x : expm1f(y.x);
        y.y = (y.y > 0.0f) ? y.y : expm1f(y.y);
        y.z = (y.z > 0.0f) ? y.z : expm1f(y.z);
        y.w = (y.w > 0.0f) ? y.w : expm1f(y.w);
    }
    reinterpret_cast<float4*>(h_sm[node])[c] = y;
    __syncthreads();

    // ---- head part 1: lin(64->32); thread computes j0=c, j1=c+16 ----
    float t0 = s_b1[c], t1 = s_b1[c + 16];
#pragma unroll
    for (int k = 0; k < 64; k++) {
        float hv = h_sm[node][k];
        t0 += hv * s_w1[k * 32 + c];
        t1 += hv * s_w1[k * 32 + c + 16];
    }
    float s = t0 + t1;
    float q = t0 * t0 + t1 * t1;
#pragma unroll
    for (int o = 8; o; o >>= 1) {
        s += __shfl_xor_sync(0xffffffffu, s, o, 16);
        q += __shfl_xor_sync(0xffffffffu, q, o, 16);
    }
    float mean = s * (1.0f / 32.0f);
    float var  = q * (1.0f / 32.0f) - mean * mean;
    float inv  = rsqrtf(var + EPS);
    t0 = (t0 - mean) * inv * s_g4[c] + s_be4[c];
    t1 = (t1 - mean) * inv * s_g4[c + 16] + s_be4[c + 16];
    t0 = (t0 > 0.0f) ? t0 : expm1f(t0);
    t1 = (t1 > 0.0f) ? t1 : expm1f(t1);
    t_sm[node][c] = t0;
    t_sm[node][c + 16] = t1;
    __syncthreads();

    // ---- head part 2: lin(32->32) ----
    if (active) {
        float o0 = s_b2[c], o1 = s_b2[c + 16];
#pragma unroll
        for (int k = 0; k < 32; k++) {
            float tv = t_sm[node][k];
            o0 += tv * s_w2[k * 32 + c];
            o1 += tv * s_w2[k * 32 + c + 16];
        }
        out[(size_t)gid * 32 + c] = o0;
        out[(size_t)gid * 32 + c + 16] = o1;
    }
}

// ---------------------------------------------------------------------
extern "C" void kernel_launch(void* const* d_in, const int* in_sizes, int n_in,
                              void* d_out, int out_size) {
    const float* x  = (const float*)d_in[0];
    const void*  ei = d_in[1];
    const float* W1 = (const float*)d_in[2];
    const float* b1 = (const float*)d_in[3];
    const float* g1 = (const float*)d_in[4];
    const float* be1 = (const float*)d_in[5];
    const float* W2 = (const float*)d_in[6];
    const float* b2 = (const float*)d_in[7];
    const float* g2 = (const float*)d_in[8];
    const float* be2 = (const float*)d_in[9];
    const float* W3 = (const float*)d_in[10];
    const float* b3 = (const float*)d_in[11];
    const float* g3 = (const float*)d_in[12];
    const float* be3 = (const float*)d_in[13];
    const float* lw1 = (const float*)d_in[14];
    const float* lb1 = (const float*)d_in[15];
    const float* g4 = (const float*)d_in[16];
    const float* be4 = (const float*)d_in[17];
    const float* lw2 = (const float*)d_in[18];
    const float* lb2 = (const float*)d_in[19];
    float* out = (float*)d_out;

    const int N = NN;
    const int E = in_sizes[1] / 2;

    void* p;
    cudaGetSymbolAddress(&p, g_bufA); float* bufA = (float*)p;
    cudaGetSymbolAddress(&p, g_bufB); float* bufB = (float*)p;

    // side stream + events, created once on the (uncaptured) first call.
    static cudaStream_t s2 = nullptr;
    static cudaEvent_t ev_fork = nullptr, ev_join = nullptr;
    if (!s2) {
        cudaStreamCreateWithFlags(&s2, cudaStreamNonBlocking);
        cudaEventCreateWithFlags(&ev_fork, cudaEventDisableTiming);
        cudaEventCreateWithFlags(&ev_join, cudaEventDisableTiming);
    }

    // ---- fork: layer-1 GEMM (independent of CSR) on side stream ----
    cudaEventRecord(ev_fork, 0);
    cudaStreamWaitEvent(s2, ev_fork, 0);
    gemm_f32x2_kernel<128, 64, 8><<<(N + 63) / 64, 256, 0, s2>>>(x, W1, nullptr, bufB, N);
    cudaEventRecord(ev_join, s2);

    // ---- graph prep: CSR build on default stream (overlapped) ----
    init_detect_kernel<<<NBLK, 256>>>(ei, E, N);
    count_deg_kernel<<<(E / 4 + 255) / 256, 256>>>(ei, E);
    scan_block_sum_kernel<<<NBLK, SCAN_CHUNK>>>(N);
    scan_boff_kernel<<<1, 512>>>(NBLK);
    scan_final_kernel<<<NBLK, SCAN_CHUNK>>>(N);
    fill_csr_kernel<<<(E + 255) / 256, 256>>>(ei, E);

    // ---- join, then layer 1 aggregation ----
    cudaStreamWaitEvent(0, ev_join, 0);
    agg_ln_elu_kernel<64><<<(N * 16 + 255) / 256, 256>>>(bufB, b1, g1, be1, bufA, N);

    // ---- layer 2: agg 64-dim, then fused GEMM 64->128 + b2 + LN + ELU ----
    agg_kernel<64><<<(N * 16 + 255) / 256, 256>>>(bufA, bufB, N);
    gemm_ln_elu_kernel<64, 128, 8><<<(N + 31) / 32, 256>>>(bufB, W2, b2, g2, be2, bufA, N);

    // ---- layer 3: GEMM 128->64, then fused agg+LN+ELU+head -> out ----
    gemm_f32x2_kernel<128, 64, 8><<<(N + 63) / 64, 256>>>(bufA, W3, nullptr, bufB, N);
    agg_ln_elu_head_kernel<<<(N + 15) / 16, 256>>>(bufB, b3, g3, be3,
                                                   lw1, lb1, g4, be4, lw2, lb2,
                                                   out, N);
}

// round 11
// speedup vs baseline: 1.0767x; 1.0767x over previous
#include <cuda_runtime.h>
#include <cstdint>

#define NN 100000
#define EMAX 1600000
#define EPS 1e-5f
#define SCAN_CHUNK 256
#define NBLK ((NN + SCAN_CHUNK - 1) / SCAN_CHUNK)   // 391

// ---- scratch (static __device__ globals; no allocation at runtime) ----
__device__ __align__(16) float g_bufA[(size_t)NN * 128];
__device__ __align__(16) float g_bufB[(size_t)NN * 128];
__device__ float g_dinv[NN];
__device__ int   g_deg[NN];
__device__ int   g_off[NN];
__device__ int   g_cur[NN];
__device__ __align__(8) int2 g_csr[EMAX];   // {src, bitcast(norm)}
__device__ int   g_bsum[512];
__device__ int   g_boff[512];
__device__ int   g_is64;

// ---------------------------------------------------------------------
// Fused: zero g_deg + detect int64 vs int32 edge_index (block 0).
__global__ void init_detect_kernel(const void* ei_raw, int E, int n_nodes) {
    int i = blockIdx.x * blockDim.x + threadIdx.x;
    if (i < n_nodes) g_deg[i] = 0;
    if (blockIdx.x == 0) {
        if (threadIdx.x == 0) g_is64 = 1;
        __syncthreads();
        const long long* e64 = (const long long*)ei_raw;
        int cnt = (2 * E < 1024) ? 2 * E : 1024;
        for (int k = threadIdx.x; k < cnt; k += blockDim.x) {
            long long v = e64[k];
            if (v < 0 || v >= n_nodes) atomicExch(&g_is64, 0);
        }
    }
}

// degree count: decode dst on the fly, 4 edges per thread
__global__ void count_deg_kernel(const void* ei_raw, int E) {
    int t = blockIdx.x * blockDim.x + threadIdx.x;
    int e0 = t * 4;
    if (e0 >= E) return;
    int cnt = (E - e0 < 4) ? (E - e0) : 4;
    if (g_is64) {
        const long long* ei = (const long long*)ei_raw;
        for (int i = 0; i < cnt; i++)
            atomicAdd(&g_deg[(int)ei[(size_t)E + e0 + i]], 1);
    } else {
        const int* ei = (const int*)ei_raw;
        if (cnt == 4) {
            int4 dv = __ldg(&reinterpret_cast<const int4*>(ei + E)[t]);
            atomicAdd(&g_deg[dv.x], 1);
            atomicAdd(&g_deg[dv.y], 1);
            atomicAdd(&g_deg[dv.z], 1);
            atomicAdd(&g_deg[dv.w], 1);
        } else {
            for (int i = 0; i < cnt; i++)
                atomicAdd(&g_deg[ei[(size_t)E + e0 + i]], 1);
        }
    }
}

// ---- 3-kernel exclusive scan of g_deg -> g_off -----------------------
__global__ void scan_block_sum_kernel(int n) {
    __shared__ int sh[SCAN_CHUNK];
    int i = blockIdx.x * SCAN_CHUNK + threadIdx.x;
    sh[threadIdx.x] = (i < n) ? g_deg[i] : 0;
    __syncthreads();
    for (int s = SCAN_CHUNK / 2; s; s >>= 1) {
        if (threadIdx.x < s) sh[threadIdx.x] += sh[threadIdx.x + s];
        __syncthreads();
    }
    if (threadIdx.x == 0) g_bsum[blockIdx.x] = sh[0];
}

__global__ void scan_boff_kernel(int nb) {
    __shared__ int sh[512];
    int v = (threadIdx.x < nb) ? g_bsum[threadIdx.x] : 0;
    sh[threadIdx.x] = v;
    __syncthreads();
    for (int o = 1; o < 512; o <<= 1) {
        int t = (threadIdx.x >= o) ? sh[threadIdx.x - o] : 0;
        __syncthreads();
        sh[threadIdx.x] += t;
        __syncthreads();
    }
    if (threadIdx.x < nb) g_boff[threadIdx.x] = sh[threadIdx.x] - v;
}

__global__ void scan_final_kernel(int n) {
    __shared__ int sh[SCAN_CHUNK];
    int i = blockIdx.x * SCAN_CHUNK + threadIdx.x;
    int v = (i < n) ? g_deg[i] : 0;
    sh[threadIdx.x] = v;
    __syncthreads();
    for (int o = 1; o < SCAN_CHUNK; o <<= 1) {
        int t = (threadIdx.x >= o) ? sh[threadIdx.x - o] : 0;
        __syncthreads();
        sh[threadIdx.x] += t;
        __syncthreads();
    }
    if (i < n) {
        int off = g_boff[blockIdx.x] + sh[threadIdx.x] - v;
        g_off[i] = off;
        g_cur[i] = off;
        g_dinv[i] = rsqrtf((float)v + 1.0f);   // fused dinv
    }
}

// CSR fill: decode edges again (no staging arrays)
__global__ void fill_csr_kernel(const void* ei_raw, int E) {
    int e = blockIdx.x * blockDim.x + threadIdx.x;
    if (e >= E) return;
    int s, d;
    if (g_is64) {
        const long long* ei = (const long long*)ei_raw;
        s = (int)ei[e];
        d = (int)ei[(size_t)E + e];
    } else {
        const int* ei = (const int*)ei_raw;
        s = __ldg(&ei[e]);
        d = __ldg(&ei[(size_t)E + e]);
    }
    int pos = atomicAdd(&g_cur[d], 1);
    float nrm = g_dinv[s] * g_dinv[d];
    g_csr[pos] = make_int2(s, __float_as_int(nrm));
}

// ---- packed-f32x2 helpers --------------------------------------------
__device__ __forceinline__ unsigned long long pkdup(float v) {
    unsigned long long r;
    asm("mov.b64 %0, {%1, %1};" : "=l"(r) : "f"(v));
    return r;
}
__device__ __forceinline__ void fma2(unsigned long long& acc,
                                     unsigned long long a,
                                     unsigned long long b) {
    asm("fma.rn.f32x2 %0, %1, %2, %0;" : "+l"(acc) : "l"(a), "l"(b));
}
__device__ __forceinline__ float2 unpk(unsigned long long v) {
    float lo, hi;
    asm("mov.b64 {%0, %1}, %2;" : "=f"(lo), "=f"(hi) : "l"(v));
    return make_float2(lo, hi);
}

// ---- plain CSR gather-accumulate (R9 form) ---------------------------
__device__ __forceinline__ void agg_loop(const float4* __restrict__ h4,
                                         int off, int deg, int G, int c,
                                         float4& acc) {
#pragma unroll 4
    for (int j = 0; j < deg; j++) {
        int2 sn = __ldg(&g_csr[off + j]);
        float w = __int_as_float(sn.y);
        float4 v = __ldg(&h4[(size_t)sn.x * G + c]);
        acc.x += v.x * w;
        acc.y += v.y * w;
        acc.z += v.z * w;
        acc.w += v.w * w;
    }
}

// ---- GEMM: C[N,Fo] = H[N,Fi] @ W[Fi,Fo] (+bias), f32x2, 4 fo/thread --
// Thread owns fo = 4*f4 .. 4*f4+3 via two packed accumulators. Weight
// pairs for both fo-pairs are one contiguous 16B LDS (natural layout).
template <int Fi, int Fo, int NPT>
__global__ void gemm_f32x2_kernel(const float* __restrict__ H,
                                  const float* __restrict__ W,
                                  const float* __restrict__ bias,
                                  float* __restrict__ C, int N) {
    constexpr int F4 = Fo / 4;
    constexpr int F2 = Fo / 2;
    constexpr int NR = 256 / F4;
    __shared__ unsigned long long Ws[Fi * F2];   // natural [k][f2] as u64
    const unsigned long long* Wu = reinterpret_cast<const unsigned long long*>(W);
    for (int i = threadIdx.x; i < Fi * F2; i += 256) Ws[i] = Wu[i];
    __syncthreads();

    int f4 = threadIdx.x % F4;
    int nr = threadIdx.x / F4;
    int n0 = blockIdx.x * (NR * NPT) + nr * NPT;

    unsigned long long accA[NPT], accB[NPT];
#pragma unroll
    for (int r = 0; r < NPT; r++) { accA[r] = 0ull; accB[r] = 0ull; }

    const float4* H4 = reinterpret_cast<const float4*>(H);
#pragma unroll 2
    for (int k4 = 0; k4 < Fi / 4; k4++) {
        ulonglong2 w0 = *reinterpret_cast<const ulonglong2*>(&Ws[(k4 * 4 + 0) * F2 + 2 * f4]);
        ulonglong2 w1 = *reinterpret_cast<const ulonglong2*>(&Ws[(k4 * 4 + 1) * F2 + 2 * f4]);
        ulonglong2 w2 = *reinterpret_cast<const ulonglong2*>(&Ws[(k4 * 4 + 2) * F2 + 2 * f4]);
        ulonglong2 w3 = *reinterpret_cast<const ulonglong2*>(&Ws[(k4 * 4 + 3) * F2 + 2 * f4]);
#pragma unroll
        for (int r = 0; r < NPT; r++) {
            int n = n0 + r;
            if (n < N) {
                float4 h = __ldg(&H4[(size_t)n * (Fi / 4) + k4]);
                unsigned long long d0 = pkdup(h.x);
                unsigned long long d1 = pkdup(h.y);
                unsigned long long d2 = pkdup(h.z);
                unsigned long long d3 = pkdup(h.w);
                fma2(accA[r], d0, w0.x); fma2(accB[r], d0, w0.y);
                fma2(accA[r], d1, w1.x); fma2(accB[r], d1, w1.y);
                fma2(accA[r], d2, w2.x); fma2(accB[r], d2, w2.y);
                fma2(accA[r], d3, w3.x); fma2(accB[r], d3, w3.y);
            }
        }
    }
    float4 bb = bias ? reinterpret_cast<const float4*>(bias)[f4]
                     : make_float4(0.0f, 0.0f, 0.0f, 0.0f);
#pragma unroll
    for (int r = 0; r < NPT; r++) {
        int n = n0 + r;
        if (n < N) {
            float2 a = unpk(accA[r]);
            float2 b = unpk(accB[r]);
            reinterpret_cast<float4*>(C)[(size_t)n * F4 + f4] =
                make_float4(a.x + bb.x, a.y + bb.y, b.x + bb.z, b.y + bb.w);
        }
    }
}

// ---- GEMM + bias + LayerNorm + ELU fused (layer 2: 64 -> 128) --------
// 4 fo/thread -> a row spans exactly one warp (F4 = 32): LN via shfl only.
template <int Fi, int Fo, int NPT>
__global__ void gemm_ln_elu_kernel(const float* __restrict__ H,
                                   const float* __restrict__ W,
                                   const float* __restrict__ bias,
                                   const float* __restrict__ gam,
                                   const float* __restrict__ bet,
                                   float* __restrict__ C, int N) {
    constexpr int F4 = Fo / 4;        // 32 = warp
    constexpr int F2 = Fo / 2;
    constexpr int NR = 256 / F4;      // 8 rows concurrently
    __shared__ unsigned long long Ws[Fi * F2];
    const unsigned long long* Wu = reinterpret_cast<const unsigned long long*>(W);
    for (int i = threadIdx.x; i < Fi * F2; i += 256) Ws[i] = Wu[i];
    __syncthreads();

    int f4 = threadIdx.x % F4;        // lane
    int nr = threadIdx.x / F4;        // warp
    int n0 = blockIdx.x * (NR * NPT) + nr * NPT;

    unsigned long long accA[NPT], accB[NPT];
#pragma unroll
    for (int r = 0; r < NPT; r++) { accA[r] = 0ull; accB[r] = 0ull; }

    const float4* H4 = reinterpret_cast<const float4*>(H);
#pragma unroll 2
    for (int k4 = 0; k4 < Fi / 4; k4++) {
        ulonglong2 w0 = *reinterpret_cast<const ulonglong2*>(&Ws[(k4 * 4 + 0) * F2 + 2 * f4]);
        ulonglong2 w1 = *reinterpret_cast<const ulonglong2*>(&Ws[(k4 * 4 + 1) * F2 + 2 * f4]);
        ulonglong2 w2 = *reinterpret_cast<const ulonglong2*>(&Ws[(k4 * 4 + 2) * F2 + 2 * f4]);
        ulonglong2 w3 = *reinterpret_cast<const ulonglong2*>(&Ws[(k4 * 4 + 3) * F2 + 2 * f4]);
#pragma unroll
        for (int r = 0; r < NPT; r++) {
            int n = n0 + r;
            if (n < N) {
                float4 h = __ldg(&H4[(size_t)n * (Fi / 4) + k4]);
                unsigned long long d0 = pkdup(h.x);
                unsigned long long d1 = pkdup(h.y);
                unsigned long long d2 = pkdup(h.z);
                unsigned long long d3 = pkdup(h.w);
                fma2(accA[r], d0, w0.x); fma2(accB[r], d0, w0.y);
                fma2(accA[r], d1, w1.x); fma2(accB[r], d1, w1.y);
                fma2(accA[r], d2, w2.x); fma2(accB[r], d2, w2.y);
                fma2(accA[r], d3, w3.x); fma2(accB[r], d3, w3.y);
            }
        }
    }

    float4 bb = reinterpret_cast<const float4*>(bias)[f4];
    float4 gg = reinterpret_cast<const float4*>(gam)[f4];
    float4 be = reinterpret_cast<const float4*>(bet)[f4];
#pragma unroll
    for (int r = 0; r < NPT; r++) {
        int n = n0 + r;
        if (n >= N) continue;
        float2 a = unpk(accA[r]);
        float2 b = unpk(accB[r]);
        float4 v = make_float4(a.x + bb.x, a.y + bb.y, b.x + bb.z, b.y + bb.w);
        float s = v.x + v.y + v.z + v.w;
        float q = v.x * v.x + v.y * v.y + v.z * v.z + v.w * v.w;
#pragma unroll
        for (int o = 16; o; o >>= 1) {
            s += __shfl_xor_sync(0xffffffffu, s, o);
            q += __shfl_xor_sync(0xffffffffu, q, o);
        }
        float mean = s * (1.0f / Fo);
        float var  = q * (1.0f / Fo) - mean * mean;
        float inv  = rsqrtf(var + EPS);
        float4 y;
        y.x = (v.x - mean) * inv * gg.x + be.x;
        y.y = (v.y - mean) * inv * gg.y + be.y;
        y.z = (v.z - mean) * inv * gg.z + be.z;
        y.w = (v.w - mean) * inv * gg.w + be.w;
        y.x = (y.x > 0.0f) ? y.x : expm1f(y.x);
        y.y = (y.y > 0.0f) ? y.y : expm1f(y.y);
        y.z = (y.z > 0.0f) ? y.z : expm1f(y.z);
        y.w = (y.w > 0.0f) ? y.w : expm1f(y.w);
        reinterpret_cast<float4*>(C)[(size_t)n * F4 + f4] = y;
    }
}

// ---- plain CSR aggregation (self-loop, no bias/LN): out = A_hat @ h --
template <int F>
__global__ void agg_kernel(const float* __restrict__ h,
                           float* __restrict__ out, int N) {
    constexpr int G = F / 4;
    int gid = (int)((blockIdx.x * blockDim.x + threadIdx.x) / G);
    int c = threadIdx.x % G;
    if (gid >= N) return;

    const float4* h4 = reinterpret_cast<const float4*>(h);
    float di = g_dinv[gid];
    float sl = di * di;
    float4 a = __ldg(&h4[(size_t)gid * G + c]);
    float4 acc = make_float4(a.x * sl, a.y * sl, a.z * sl, a.w * sl);

    agg_loop(h4, g_off[gid], g_deg[gid], G, c, acc);

    reinterpret_cast<float4*>(out)[(size_t)gid * G + c] = acc;
}

// ---- fused CSR aggregation + self-loop + bias + LayerNorm + ELU ------
template <int F>
__global__ void agg_ln_elu_kernel(const float* __restrict__ xw,
                                  const float* __restrict__ bias,
                                  const float* __restrict__ gam,
                                  const float* __restrict__ bet,
                                  float* __restrict__ out, int N) {
    constexpr int G = F / 4;
    int gid = (int)((blockIdx.x * blockDim.x + threadIdx.x) / G);
    int c = threadIdx.x % G;
    if (gid >= N) return;

    const float4* xw4 = reinterpret_cast<const float4*>(xw);
    float di = g_dinv[gid];
    float sl = di * di;
    float4 a = __ldg(&xw4[(size_t)gid * G + c]);
    float4 acc = make_float4(a.x * sl, a.y * sl, a.z * sl, a.w * sl);

    agg_loop(xw4, g_off[gid], g_deg[gid], G, c, acc);

    float4 bb = __ldg(&reinterpret_cast<const float4*>(bias)[c]);
    acc.x += bb.x; acc.y += bb.y; acc.z += bb.z; acc.w += bb.w;

    float sum = acc.x + acc.y + acc.z + acc.w;
    float sq  = acc.x * acc.x + acc.y * acc.y + acc.z * acc.z + acc.w * acc.w;
#pragma unroll
    for (int o = G / 2; o; o >>= 1) {
        sum += __shfl_xor_sync(0xffffffffu, sum, o);
        sq  += __shfl_xor_sync(0xffffffffu, sq, o);
    }
    float mean = sum * (1.0f / F);
    float var  = sq * (1.0f / F) - mean * mean;
    float inv  = rsqrtf(var + EPS);

    float4 gg = __ldg(&reinterpret_cast<const float4*>(gam)[c]);
    float4 be = __ldg(&reinterpret_cast<const float4*>(bet)[c]);
    float4 y;
    y.x = (acc.x - mean) * inv * gg.x + be.x;
    y.y = (acc.y - mean) * inv * gg.y + be.y;
    y.z = (acc.z - mean) * inv * gg.z + be.z;
    y.w = (acc.w - mean) * inv * gg.w + be.w;
    y.x = (y.x > 0.0f) ? y.x : expm1f(y.x);
    y.y = (y.y > 0.0f) ? y.y : expm1f(y.y);
    y.z = (y.z > 0.0f) ? y.z : expm1f(y.z);
    y.w = (y.w > 0.0f) ? y.w : expm1f(y.w);
    reinterpret_cast<float4*>(out)[(size_t)gid * G + c] = y;
}

// ---- layer 3 + head fully fused:
// agg(64) + b3 + LN + ELU + lin(64->32) + LN + ELU + lin(32->32) -> out
__global__ void agg_ln_elu_head_kernel(const float* __restrict__ xw,
                                       const float* __restrict__ bias,
                                       const float* __restrict__ gam,
                                       const float* __restrict__ bet,
                                       const float* __restrict__ lw1,
                                       const float* __restrict__ lb1,
                                       const float* __restrict__ g4,
                                       const float* __restrict__ be4,
                                       const float* __restrict__ lw2,
                                       const float* __restrict__ lb2,
                                       float* __restrict__ out, int N) {
    constexpr int G = 16;             // threads per node (F=64)
    constexpr int NODES = 256 / G;    // 16 nodes per block
    __shared__ float s_w1[64 * 32];
    __shared__ float s_w2[32 * 32];
    __shared__ float s_b1[32], s_g4[32], s_be4[32], s_b2[32];
    __shared__ float h_sm[NODES][64];
    __shared__ float t_sm[NODES][32];

    for (int i = threadIdx.x; i < 64 * 32; i += 256) s_w1[i] = lw1[i];
    for (int i = threadIdx.x; i < 32 * 32; i += 256) s_w2[i] = lw2[i];
    if (threadIdx.x < 32) {
        s_b1[threadIdx.x]  = lb1[threadIdx.x];
        s_g4[threadIdx.x]  = g4[threadIdx.x];
        s_be4[threadIdx.x] = be4[threadIdx.x];
        s_b2[threadIdx.x]  = lb2[threadIdx.x];
    }
    __syncthreads();

    int node = threadIdx.x / G;       // node slot within block
    int c    = threadIdx.x % G;
    int gid  = blockIdx.x * NODES + node;
    bool active = (gid < N);

    float4 y = make_float4(0.0f, 0.0f, 0.0f, 0.0f);
    if (active) {
        const float4* xw4 = reinterpret_cast<const float4*>(xw);
        float di = g_dinv[gid];
        float sl = di * di;
        float4 a = __ldg(&xw4[(size_t)gid * G + c]);
        float4 acc = make_float4(a.x * sl, a.y * sl, a.z * sl, a.w * sl);

        agg_loop(xw4, g_off[gid], g_deg[gid], G, c, acc);

        float4 bb = __ldg(&reinterpret_cast<const float4*>(bias)[c]);
        acc.x += bb.x; acc.y += bb.y; acc.z += bb.z; acc.w += bb.w;

        float sum = acc.x + acc.y + acc.z + acc.w;
        float sq  = acc.x * acc.x + acc.y * acc.y + acc.z * acc.z + acc.w * acc.w;
#pragma unroll
        for (int o = 8; o; o >>= 1) {
            sum += __shfl_xor_sync(0xffffffffu, sum, o, 16);
            sq  += __shfl_xor_sync(0xffffffffu, sq, o, 16);
        }
        float mean = sum * (1.0f / 64.0f);
        float var  = sq * (1.0f / 64.0f) - mean * mean;
        float inv  = rsqrtf(var + EPS);

        float4 gg = __ldg(&reinterpret_cast<const float4*>(gam)[c]);
        float4 be = __ldg(&reinterpret_cast<const float4*>(bet)[c]);
        y.x = (acc.x - mean) * inv * gg.x + be.x;
        y.y = (acc.y - mean) * inv * gg.y + be.y;
        y.z = (acc.z - mean) * inv * gg.z + be.z;
        y.w = (acc.w - mean) * inv * gg.w + be.w;
        y.x = (y.x > 0.0f) ? y.x : expm1f(y.x);
        y.y = (y.y > 0.0f) ? y.y : expm1f(y.y);
        y.z = (y.z > 0.0f) ? y.z : expm1f(y.z);
        y.w = (y.w > 0.0f) ? y.w : expm1f(y.w);
    }
    reinterpret_cast<float4*>(h_sm[node])[c] = y;
    __syncthreads();

    // ---- head part 1: lin(64->32); thread computes j0=c, j1=c+16 ----
    float t0 = s_b1[c], t1 = s_b1[c + 16];
#pragma unroll
    for (int k = 0; k < 64; k++) {
        float hv = h_sm[node][k];
        t0 += hv * s_w1[k * 32 + c];
        t1 += hv * s_w1[k * 32 + c + 16];
    }
    float s = t0 + t1;
    float q = t0 * t0 + t1 * t1;
#pragma unroll
    for (int o = 8; o; o >>= 1) {
        s += __shfl_xor_sync(0xffffffffu, s, o, 16);
        q += __shfl_xor_sync(0xffffffffu, q, o, 16);
    }
    float mean = s * (1.0f / 32.0f);
    float var  = q * (1.0f / 32.0f) - mean * mean;
    float inv  = rsqrtf(var + EPS);
    t0 = (t0 - mean) * inv * s_g4[c] + s_be4[c];
    t1 = (t1 - mean) * inv * s_g4[c + 16] + s_be4[c + 16];
    t0 = (t0 > 0.0f) ? t0 : expm1f(t0);
    t1 = (t1 > 0.0f) ? t1 : expm1f(t1);
    t_sm[node][c] = t0;
    t_sm[node][c + 16] = t1;
    __syncthreads();

    // ---- head part 2: lin(32->32) ----
    if (active) {
        float o0 = s_b2[c], o1 = s_b2[c + 16];
#pragma unroll
        for (int k = 0; k < 32; k++) {
            float tv = t_sm[node][k];
            o0 += tv * s_w2[k * 32 + c];
            o1 += tv * s_w2[k * 32 + c + 16];
        }
        out[(size_t)gid * 32 + c] = o0;
        out[(size_t)gid * 32 + c + 16] = o1;
    }
}

// ---------------------------------------------------------------------
extern "C" void kernel_launch(void* const* d_in, const int* in_sizes, int n_in,
                              void* d_out, int out_size) {
    const float* x  = (const float*)d_in[0];
    const void*  ei = d_in[1];
    const float* W1 = (const float*)d_in[2];
    const float* b1 = (const float*)d_in[3];
    const float* g1 = (const float*)d_in[4];
    const float* be1 = (const float*)d_in[5];
    const float* W2 = (const float*)d_in[6];
    const float* b2 = (const float*)d_in[7];
    const float* g2 = (const float*)d_in[8];
    const float* be2 = (const float*)d_in[9];
    const float* W3 = (const float*)d_in[10];
    const float* b3 = (const float*)d_in[11];
    const float* g3 = (const float*)d_in[12];
    const float* be3 = (const float*)d_in[13];
    const float* lw1 = (const float*)d_in[14];
    const float* lb1 = (const float*)d_in[15];
    const float* g4 = (const float*)d_in[16];
    const float* be4 = (const float*)d_in[17];
    const float* lw2 = (const float*)d_in[18];
    const float* lb2 = (const float*)d_in[19];
    float* out = (float*)d_out;

    const int N = NN;
    const int E = in_sizes[1] / 2;

    void* p;
    cudaGetSymbolAddress(&p, g_bufA); float* bufA = (float*)p;
    cudaGetSymbolAddress(&p, g_bufB); float* bufB = (float*)p;

    // side stream + events, created once on the (uncaptured) first call.
    static cudaStream_t s2 = nullptr;
    static cudaEvent_t ev_fork = nullptr, ev_join = nullptr;
    if (!s2) {
        cudaStreamCreateWithFlags(&s2, cudaStreamNonBlocking);
        cudaEventCreateWithFlags(&ev_fork, cudaEventDisableTiming);
        cudaEventCreateWithFlags(&ev_join, cudaEventDisableTiming);
    }

    // ---- fork: layer-1 GEMM (independent of CSR) on side stream ----
    // Fo=64: F4=16 -> 16 rows concurrent x NPT=8 -> 128 rows/block
    cudaEventRecord(ev_fork, 0);
    cudaStreamWaitEvent(s2, ev_fork, 0);
    gemm_f32x2_kernel<128, 64, 8><<<(N + 127) / 128, 256, 0, s2>>>(x, W1, nullptr, bufB, N);
    cudaEventRecord(ev_join, s2);

    // ---- graph prep: CSR build on default stream (overlapped) ----
    init_detect_kernel<<<NBLK, 256>>>(ei, E, N);
    count_deg_kernel<<<(E / 4 + 255) / 256, 256>>>(ei, E);
    scan_block_sum_kernel<<<NBLK, SCAN_CHUNK>>>(N);
    scan_boff_kernel<<<1, 512>>>(NBLK);
    scan_final_kernel<<<NBLK, SCAN_CHUNK>>>(N);
    fill_csr_kernel<<<(E + 255) / 256, 256>>>(ei, E);

    // ---- join, then layer 1 aggregation ----
    cudaStreamWaitEvent(0, ev_join, 0);
    agg_ln_elu_kernel<64><<<(N * 16 + 255) / 256, 256>>>(bufB, b1, g1, be1, bufA, N);

    // ---- layer 2: agg 64-dim, then fused GEMM 64->128 + b2 + LN + ELU ----
    // Fo=128: F4=32 (warp/row), 8 rows x NPT=8 -> 64 rows/block
    agg_kernel<64><<<(N * 16 + 255) / 256, 256>>>(bufA, bufB, N);
    gemm_ln_elu_kernel<64, 128, 8><<<(N + 63) / 64, 256>>>(bufB, W2, b2, g2, be2, bufA, N);

    // ---- layer 3: GEMM 128->64, then fused agg+LN+ELU+head -> out ----
    gemm_f32x2_kernel<128, 64, 8><<<(N + 127) / 128, 256>>>(bufA, W3, nullptr, bufB, N);
    agg_ln_elu_head_kernel<<<(N + 15) / 16, 256>>>(bufB, b3, g3, be3,
                                                   lw1, lb1, g4, be4, lw2, lb2,
                                                   out, N);
}

// round 12
// speedup vs baseline: 1.0889x; 1.0114x over previous
#include <cuda_runtime.h>
#include <cstdint>

#define NN 100000
#define EMAX 1600000
#define EPS 1e-5f
#define SCAN_CHUNK 256
#define NBLK ((NN + SCAN_CHUNK - 1) / SCAN_CHUNK)   // 391

// ---- scratch (static __device__ globals; no allocation at runtime) ----
__device__ __align__(16) float g_bufA[(size_t)NN * 128];
__device__ __align__(16) float g_bufB[(size_t)NN * 128];
__device__ float g_dinv[NN];
__device__ int   g_deg[NN];
__device__ int   g_off[NN];
__device__ int   g_cur[NN];
__device__ __align__(8) int2 g_csr[EMAX];   // {src, bitcast(norm)}
__device__ int   g_bsum[512];
__device__ int   g_boff[512];
__device__ int   g_is64;

// ---------------------------------------------------------------------
// Fused: zero g_deg + detect int64 vs int32 edge_index (block 0).
__global__ void init_detect_kernel(const void* ei_raw, int E, int n_nodes) {
    int i = blockIdx.x * blockDim.x + threadIdx.x;
    if (i < n_nodes) g_deg[i] = 0;
    if (blockIdx.x == 0) {
        if (threadIdx.x == 0) g_is64 = 1;
        __syncthreads();
        const long long* e64 = (const long long*)ei_raw;
        int cnt = (2 * E < 1024) ? 2 * E : 1024;
        for (int k = threadIdx.x; k < cnt; k += blockDim.x) {
            long long v = e64[k];
            if (v < 0 || v >= n_nodes) atomicExch(&g_is64, 0);
        }
    }
}

// degree count: decode dst on the fly, 4 edges per thread
__global__ void count_deg_kernel(const void* ei_raw, int E) {
    int t = blockIdx.x * blockDim.x + threadIdx.x;
    int e0 = t * 4;
    if (e0 >= E) return;
    int cnt = (E - e0 < 4) ? (E - e0) : 4;
    if (g_is64) {
        const long long* ei = (const long long*)ei_raw;
        for (int i = 0; i < cnt; i++)
            atomicAdd(&g_deg[(int)ei[(size_t)E + e0 + i]], 1);
    } else {
        const int* ei = (const int*)ei_raw;
        if (cnt == 4) {
            int4 dv = __ldg(&reinterpret_cast<const int4*>(ei + E)[t]);
            atomicAdd(&g_deg[dv.x], 1);
            atomicAdd(&g_deg[dv.y], 1);
            atomicAdd(&g_deg[dv.z], 1);
            atomicAdd(&g_deg[dv.w], 1);
        } else {
            for (int i = 0; i < cnt; i++)
                atomicAdd(&g_deg[ei[(size_t)E + e0 + i]], 1);
        }
    }
}

// ---- 3-kernel exclusive scan of g_deg -> g_off -----------------------
__global__ void scan_block_sum_kernel(int n) {
    __shared__ int sh[SCAN_CHUNK];
    int i = blockIdx.x * SCAN_CHUNK + threadIdx.x;
    sh[threadIdx.x] = (i < n) ? g_deg[i] : 0;
    __syncthreads();
    for (int s = SCAN_CHUNK / 2; s; s >>= 1) {
        if (threadIdx.x < s) sh[threadIdx.x] += sh[threadIdx.x + s];
        __syncthreads();
    }
    if (threadIdx.x == 0) g_bsum[blockIdx.x] = sh[0];
}

__global__ void scan_boff_kernel(int nb) {
    __shared__ int sh[512];
    int v = (threadIdx.x < nb) ? g_bsum[threadIdx.x] : 0;
    sh[threadIdx.x] = v;
    __syncthreads();
    for (int o = 1; o < 512; o <<= 1) {
        int t = (threadIdx.x >= o) ? sh[threadIdx.x - o] : 0;
        __syncthreads();
        sh[threadIdx.x] += t;
        __syncthreads();
    }
    if (threadIdx.x < nb) g_boff[threadIdx.x] = sh[threadIdx.x] - v;
}

__global__ void scan_final_kernel(int n) {
    __shared__ int sh[SCAN_CHUNK];
    int i = blockIdx.x * SCAN_CHUNK + threadIdx.x;
    int v = (i < n) ? g_deg[i] : 0;
    sh[threadIdx.x] = v;
    __syncthreads();
    for (int o = 1; o < SCAN_CHUNK; o <<= 1) {
        int t = (threadIdx.x >= o) ? sh[threadIdx.x - o] : 0;
        __syncthreads();
        sh[threadIdx.x] += t;
        __syncthreads();
    }
    if (i < n) {
        int off = g_boff[blockIdx.x] + sh[threadIdx.x] - v;
        g_off[i] = off;
        g_cur[i] = off;
        g_dinv[i] = rsqrtf((float)v + 1.0f);   // fused dinv
    }
}

// CSR fill: decode edges again (no staging arrays)
__global__ void fill_csr_kernel(const void* ei_raw, int E) {
    int e = blockIdx.x * blockDim.x + threadIdx.x;
    if (e >= E) return;
    int s, d;
    if (g_is64) {
        const long long* ei = (const long long*)ei_raw;
        s = (int)ei[e];
        d = (int)ei[(size_t)E + e];
    } else {
        const int* ei = (const int*)ei_raw;
        s = __ldg(&ei[e]);
        d = __ldg(&ei[(size_t)E + e]);
    }
    int pos = atomicAdd(&g_cur[d], 1);
    float nrm = g_dinv[s] * g_dinv[d];
    g_csr[pos] = make_int2(s, __float_as_int(nrm));
}

// ---- packed-f32x2 helpers --------------------------------------------
__device__ __forceinline__ unsigned long long pkdup(float v) {
    unsigned long long r;
    asm("mov.b64 %0, {%1, %1};" : "=l"(r) : "f"(v));
    return r;
}
__device__ __forceinline__ void fma2(unsigned long long& acc,
                                     unsigned long long a,
                                     unsigned long long b) {
    asm("fma.rn.f32x2 %0, %1, %2, %0;" : "+l"(acc) : "l"(a), "l"(b));
}
__device__ __forceinline__ float2 unpk(unsigned long long v) {
    float lo, hi;
    asm("mov.b64 {%0, %1}, %2;" : "=f"(lo), "=f"(hi) : "l"(v));
    return make_float2(lo, hi);
}

// ---- packed CSR gather-accumulate: 6 instr/edge/thread ---------------
// Gathered 16B chunk consumed directly as two u64 f32x2 operands (no
// pack MOVs); only the weight needs one dup MOV. Lane-wise arithmetic
// identical to scalar FFMA (same accumulation order per float).
__device__ __forceinline__ void agg_loop(const float4* __restrict__ h4,
                                         int off, int deg, int G, int c,
                                         unsigned long long& accA,
                                         unsigned long long& accB) {
    const ulonglong2* h8 = reinterpret_cast<const ulonglong2*>(h4);
#pragma unroll 4
    for (int j = 0; j < deg; j++) {
        int2 sn = __ldg(&g_csr[off + j]);
        unsigned long long w2 = pkdup(__int_as_float(sn.y));
        ulonglong2 v = __ldg(&h8[(size_t)sn.x * G + c]);
        fma2(accA, v.x, w2);
        fma2(accB, v.y, w2);
    }
}

// Packed self-loop init: acc = a * sl (via fma into zero accumulator).
__device__ __forceinline__ void agg_init(const float4* __restrict__ h4,
                                         int gid, int G, int c, float sl,
                                         unsigned long long& accA,
                                         unsigned long long& accB) {
    const ulonglong2* h8 = reinterpret_cast<const ulonglong2*>(h4);
    ulonglong2 a = __ldg(&h8[(size_t)gid * G + c]);
    unsigned long long sl2 = pkdup(sl);
    accA = 0ull; accB = 0ull;
    fma2(accA, a.x, sl2);
    fma2(accB, a.y, sl2);
}

// ---- GEMM: C[N,Fo] = H[N,Fi] @ W[Fi,Fo] (+bias), f32x2, 4 fo/thread --
template <int Fi, int Fo, int NPT>
__global__ void gemm_f32x2_kernel(const float* __restrict__ H,
                                  const float* __restrict__ W,
                                  const float* __restrict__ bias,
                                  float* __restrict__ C, int N) {
    constexpr int F4 = Fo / 4;
    constexpr int F2 = Fo / 2;
    constexpr int NR = 256 / F4;
    __shared__ unsigned long long Ws[Fi * F2];   // natural [k][f2] as u64
    const unsigned long long* Wu = reinterpret_cast<const unsigned long long*>(W);
    for (int i = threadIdx.x; i < Fi * F2; i += 256) Ws[i] = Wu[i];
    __syncthreads();

    int f4 = threadIdx.x % F4;
    int nr = threadIdx.x / F4;
    int n0 = blockIdx.x * (NR * NPT) + nr * NPT;

    unsigned long long accA[NPT], accB[NPT];
#pragma unroll
    for (int r = 0; r < NPT; r++) { accA[r] = 0ull; accB[r] = 0ull; }

    const float4* H4 = reinterpret_cast<const float4*>(H);
#pragma unroll 2
    for (int k4 = 0; k4 < Fi / 4; k4++) {
        ulonglong2 w0 = *reinterpret_cast<const ulonglong2*>(&Ws[(k4 * 4 + 0) * F2 + 2 * f4]);
        ulonglong2 w1 = *reinterpret_cast<const ulonglong2*>(&Ws[(k4 * 4 + 1) * F2 + 2 * f4]);
        ulonglong2 w2 = *reinterpret_cast<const ulonglong2*>(&Ws[(k4 * 4 + 2) * F2 + 2 * f4]);
        ulonglong2 w3 = *reinterpret_cast<const ulonglong2*>(&Ws[(k4 * 4 + 3) * F2 + 2 * f4]);
#pragma unroll
        for (int r = 0; r < NPT; r++) {
            int n = n0 + r;
            if (n < N) {
                float4 h = __ldg(&H4[(size_t)n * (Fi / 4) + k4]);
                unsigned long long d0 = pkdup(h.x);
                unsigned long long d1 = pkdup(h.y);
                unsigned long long d2 = pkdup(h.z);
                unsigned long long d3 = pkdup(h.w);
                fma2(accA[r], d0, w0.x); fma2(accB[r], d0, w0.y);
                fma2(accA[r], d1, w1.x); fma2(accB[r], d1, w1.y);
                fma2(accA[r], d2, w2.x); fma2(accB[r], d2, w2.y);
                fma2(accA[r], d3, w3.x); fma2(accB[r], d3, w3.y);
            }
        }
    }
    float4 bb = bias ? reinterpret_cast<const float4*>(bias)[f4]
                     : make_float4(0.0f, 0.0f, 0.0f, 0.0f);
#pragma unroll
    for (int r = 0; r < NPT; r++) {
        int n = n0 + r;
        if (n < N) {
            float2 a = unpk(accA[r]);
            float2 b = unpk(accB[r]);
            reinterpret_cast<float4*>(C)[(size_t)n * F4 + f4] =
                make_float4(a.x + bb.x, a.y + bb.y, b.x + bb.z, b.y + bb.w);
        }
    }
}

// ---- GEMM + bias + LayerNorm + ELU fused (layer 2: 64 -> 128) --------
template <int Fi, int Fo, int NPT>
__global__ void gemm_ln_elu_kernel(const float* __restrict__ H,
                                   const float* __restrict__ W,
                                   const float* __restrict__ bias,
                                   const float* __restrict__ gam,
                                   const float* __restrict__ bet,
                                   float* __restrict__ C, int N) {
    constexpr int F4 = Fo / 4;        // 32 = warp
    constexpr int F2 = Fo / 2;
    constexpr int NR = 256 / F4;      // 8 rows concurrently
    __shared__ unsigned long long Ws[Fi * F2];
    const unsigned long long* Wu = reinterpret_cast<const unsigned long long*>(W);
    for (int i = threadIdx.x; i < Fi * F2; i += 256) Ws[i] = Wu[i];
    __syncthreads();

    int f4 = threadIdx.x % F4;        // lane
    int nr = threadIdx.x / F4;        // warp
    int n0 = blockIdx.x * (NR * NPT) + nr * NPT;

    unsigned long long accA[NPT], accB[NPT];
#pragma unroll
    for (int r = 0; r < NPT; r++) { accA[r] = 0ull; accB[r] = 0ull; }

    const float4* H4 = reinterpret_cast<const float4*>(H);
#pragma unroll 2
    for (int k4 = 0; k4 < Fi / 4; k4++) {
        ulonglong2 w0 = *reinterpret_cast<const ulonglong2*>(&Ws[(k4 * 4 + 0) * F2 + 2 * f4]);
        ulonglong2 w1 = *reinterpret_cast<const ulonglong2*>(&Ws[(k4 * 4 + 1) * F2 + 2 * f4]);
        ulonglong2 w2 = *reinterpret_cast<const ulonglong2*>(&Ws[(k4 * 4 + 2) * F2 + 2 * f4]);
        ulonglong2 w3 = *reinterpret_cast<const ulonglong2*>(&Ws[(k4 * 4 + 3) * F2 + 2 * f4]);
#pragma unroll
        for (int r = 0; r < NPT; r++) {
            int n = n0 + r;
            if (n < N) {
                float4 h = __ldg(&H4[(size_t)n * (Fi / 4) + k4]);
                unsigned long long d0 = pkdup(h.x);
                unsigned long long d1 = pkdup(h.y);
                unsigned long long d2 = pkdup(h.z);
                unsigned long long d3 = pkdup(h.w);
                fma2(accA[r], d0, w0.x); fma2(accB[r], d0, w0.y);
                fma2(accA[r], d1, w1.x); fma2(accB[r], d1, w1.y);
                fma2(accA[r], d2, w2.x); fma2(accB[r], d2, w2.y);
                fma2(accA[r], d3, w3.x); fma2(accB[r], d3, w3.y);
            }
        }
    }

    float4 bb = reinterpret_cast<const float4*>(bias)[f4];
    float4 gg = reinterpret_cast<const float4*>(gam)[f4];
    float4 be = reinterpret_cast<const float4*>(bet)[f4];
#pragma unroll
    for (int r = 0; r < NPT; r++) {
        int n = n0 + r;
        if (n >= N) continue;
        float2 a = unpk(accA[r]);
        float2 b = unpk(accB[r]);
        float4 v = make_float4(a.x + bb.x, a.y + bb.y, b.x + bb.z, b.y + bb.w);
        float s = v.x + v.y + v.z + v.w;
        float q = v.x * v.x + v.y * v.y + v.z * v.z + v.w * v.w;
#pragma unroll
        for (int o = 16; o; o >>= 1) {
            s += __shfl_xor_sync(0xffffffffu, s, o);
            q += __shfl_xor_sync(0xffffffffu, q, o);
        }
        float mean = s * (1.0f / Fo);
        float var  = q * (1.0f / Fo) - mean * mean;
        float inv  = rsqrtf(var + EPS);
        float4 y;
        y.x = (v.x - mean) * inv * gg.x + be.x;
        y.y = (v.y - mean) * inv * gg.y + be.y;
        y.z = (v.z - mean) * inv * gg.z + be.z;
        y.w = (v.w - mean) * inv * gg.w + be.w;
        y.x = (y.x > 0.0f) ? y.x : expm1f(y.x);
        y.y = (y.y > 0.0f) ? y.y : expm1f(y.y);
        y.z = (y.z > 0.0f) ? y.z : expm1f(y.z);
        y.w = (y.w > 0.0f) ? y.w : expm1f(y.w);
        reinterpret_cast<float4*>(C)[(size_t)n * F4 + f4] = y;
    }
}

// ---- plain CSR aggregation (self-loop, no bias/LN): out = A_hat @ h --
template <int F>
__global__ void agg_kernel(const float* __restrict__ h,
                           float* __restrict__ out, int N) {
    constexpr int G = F / 4;
    int gid = (int)((blockIdx.x * blockDim.x + threadIdx.x) / G);
    int c = threadIdx.x % G;
    if (gid >= N) return;

    const float4* h4 = reinterpret_cast<const float4*>(h);
    float di = g_dinv[gid];
    unsigned long long accA, accB;
    agg_init(h4, gid, G, c, di * di, accA, accB);
    agg_loop(h4, g_off[gid], g_deg[gid], G, c, accA, accB);

    float2 a = unpk(accA);
    float2 b = unpk(accB);
    reinterpret_cast<float4*>(out)[(size_t)gid * G + c] =
        make_float4(a.x, a.y, b.x, b.y);
}

// ---- fused CSR aggregation + self-loop + bias + LayerNorm + ELU ------
template <int F>
__global__ void agg_ln_elu_kernel(const float* __restrict__ xw,
                                  const float* __restrict__ bias,
                                  const float* __restrict__ gam,
                                  const float* __restrict__ bet,
                                  float* __restrict__ out, int N) {
    constexpr int G = F / 4;
    int gid = (int)((blockIdx.x * blockDim.x + threadIdx.x) / G);
    int c = threadIdx.x % G;
    if (gid >= N) return;

    const float4* xw4 = reinterpret_cast<const float4*>(xw);
    float di = g_dinv[gid];
    unsigned long long accA, accB;
    agg_init(xw4, gid, G, c, di * di, accA, accB);
    agg_loop(xw4, g_off[gid], g_deg[gid], G, c, accA, accB);

    float2 pa = unpk(accA);
    float2 pb = unpk(accB);
    float4 acc = make_float4(pa.x, pa.y, pb.x, pb.y);

    float4 bb = __ldg(&reinterpret_cast<const float4*>(bias)[c]);
    acc.x += bb.x; acc.y += bb.y; acc.z += bb.z; acc.w += bb.w;

    float sum = acc.x + acc.y + acc.z + acc.w;
    float sq  = acc.x * acc.x + acc.y * acc.y + acc.z * acc.z + acc.w * acc.w;
#pragma unroll
    for (int o = G / 2; o; o >>= 1) {
        sum += __shfl_xor_sync(0xffffffffu, sum, o);
        sq  += __shfl_xor_sync(0xffffffffu, sq, o);
    }
    float mean = sum * (1.0f / F);
    float var  = sq * (1.0f / F) - mean * mean;
    float inv  = rsqrtf(var + EPS);

    float4 gg = __ldg(&reinterpret_cast<const float4*>(gam)[c]);
    float4 be = __ldg(&reinterpret_cast<const float4*>(bet)[c]);
    float4 y;
    y.x = (acc.x - mean) * inv * gg.x + be.x;
    y.y = (acc.y - mean) * inv * gg.y + be.y;
    y.z = (acc.z - mean) * inv * gg.z + be.z;
    y.w = (acc.w - mean) * inv * gg.w + be.w;
    y.x = (y.x > 0.0f) ? y.x : expm1f(y.x);
    y.y = (y.y > 0.0f) ? y.y : expm1f(y.y);
    y.z = (y.z > 0.0f) ? y.z : expm1f(y.z);
    y.w = (y.w > 0.0f) ? y.w : expm1f(y.w);
    reinterpret_cast<float4*>(out)[(size_t)gid * G + c] = y;
}

// ---- layer 3 + head fully fused:
// agg(64) + b3 + LN + ELU + lin(64->32) + LN + ELU + lin(32->32) -> out
__global__ void agg_ln_elu_head_kernel(const float* __restrict__ xw,
                                       const float* __restrict__ bias,
                                       const float* __restrict__ gam,
                                       const float* __restrict__ bet,
                                       const float* __restrict__ lw1,
                                       const float* __restrict__ lb1,
                                       const float* __restrict__ g4,
                                       const float* __restrict__ be4,
                                       const float* __restrict__ lw2,
                                       const float* __restrict__ lb2,
                                       float* __restrict__ out, int N) {
    constexpr int G = 16;             // threads per node (F=64)
    constexpr int NODES = 256 / G;    // 16 nodes per block
    __shared__ float s_w1[64 * 32];
    __shared__ float s_w2[32 * 32];
    __shared__ float s_b1[32], s_g4[32], s_be4[32], s_b2[32];
    __shared__ float h_sm[NODES][64];
    __shared__ float t_sm[NODES][32];

    for (int i = threadIdx.x; i < 64 * 32; i += 256) s_w1[i] = lw1[i];
    for (int i = threadIdx.x; i < 32 * 32; i += 256) s_w2[i] = lw2[i];
    if (threadIdx.x < 32) {
        s_b1[threadIdx.x]  = lb1[threadIdx.x];
        s_g4[threadIdx.x]  = g4[threadIdx.x];
        s_be4[threadIdx.x] = be4[threadIdx.x];
        s_b2[threadIdx.x]  = lb2[threadIdx.x];
    }
    __syncthreads();

    int node = threadIdx.x / G;       // node slot within block
    int c    = threadIdx.x % G;
    int gid  = blockIdx.x * NODES + node;
    bool active = (gid < N);

    float4 y = make_float4(0.0f, 0.0f, 0.0f, 0.0f);
    if (active) {
        const float4* xw4 = reinterpret_cast<const float4*>(xw);
        float di = g_dinv[gid];
        unsigned long long accA, accB;
        agg_init(xw4, gid, G, c, di * di, accA, accB);
        agg_loop(xw4, g_off[gid], g_deg[gid], G, c, accA, accB);

        float2 pa = unpk(accA);
        float2 pb = unpk(accB);
        float4 acc = make_float4(pa.x, pa.y, pb.x, pb.y);

        float4 bb = __ldg(&reinterpret_cast<const float4*>(bias)[c]);
        acc.x += bb.x; acc.y += bb.y; acc.z += bb.z; acc.w += bb.w;

        float sum = acc.x + acc.y + acc.z + acc.w;
        float sq  = acc.x * acc.x + acc.y * acc.y + acc.z * acc.z + acc.w * acc.w;
#pragma unroll
        for (int o = 8; o; o >>= 1) {
            sum += __shfl_xor_sync(0xffffffffu, sum, o, 16);
            sq  += __shfl_xor_sync(0xffffffffu, sq, o, 16);
        }
        float mean = sum * (1.0f / 64.0f);
        float var  = sq * (1.0f / 64.0f) - mean * mean;
        float inv  = rsqrtf(var + EPS);

        float4 gg = __ldg(&reinterpret_cast<const float4*>(gam)[c]);
        float4 be = __ldg(&reinterpret_cast<const float4*>(bet)[c]);
        y.x = (acc.x - mean) * inv * gg.x + be.x;
        y.y = (acc.y - mean) * inv * gg.y + be.y;
        y.z = (acc.z - mean) * inv * gg.z + be.z;
        y.w = (acc.w - mean) * inv * gg.w + be.w;
        y.x = (y.x > 0.0f) ? y.x : expm1f(y.x);
        y.y = (y.y > 0.0f) ? y.y : expm1f(y.y);
        y.z = (y.z > 0.0f) ? y.z : expm1f(y.z);
        y.w = (y.w > 0.0f) ? y.w : expm1f(y.w);
    }
    reinterpret_cast<float4*>(h_sm[node])[c] = y;
    __syncthreads();

    // ---- head part 1: lin(64->32); thread computes j0=c, j1=c+16 ----
    float t0 = s_b1[c], t1 = s_b1[c + 16];
#pragma unroll
    for (int k = 0; k < 64; k++) {
        float hv = h_sm[node][k];
        t0 += hv * s_w1[k * 32 + c];
        t1 += hv * s_w1[k * 32 + c + 16];
    }
    float s = t0 + t1;
    float q = t0 * t0 + t1 * t1;
#pragma unroll
    for (int o = 8; o; o >>= 1) {
        s += __shfl_xor_sync(0xffffffffu, s, o, 16);
        q += __shfl_xor_sync(0xffffffffu, q, o, 16);
    }
    float mean = s * (1.0f / 32.0f);
    float var  = q * (1.0f / 32.0f) - mean * mean;
    float inv  = rsqrtf(var + EPS);
    t0 = (t0 - mean) * inv * s_g4[c] + s_be4[c];
    t1 = (t1 - mean) * inv * s_g4[c + 16] + s_be4[c + 16];
    t0 = (t0 > 0.0f) ? t0 : expm1f(t0);
    t1 = (t1 > 0.0f) ? t1 : expm1f(t1);
    t_sm[node][c] = t0;
    t_sm[node][c + 16] = t1;
    __syncthreads();

    // ---- head part 2: lin(32->32) ----
    if (active) {
        float o0 = s_b2[c], o1 = s_b2[c + 16];
#pragma unroll
        for (int k = 0; k < 32; k++) {
            float tv = t_sm[node][k];
            o0 += tv * s_w2[k * 32 + c];
            o1 += tv * s_w2[k * 32 + c + 16];
        }
        out[(size_t)gid * 32 + c] = o0;
        out[(size_t)gid * 32 + c + 16] = o1;
    }
}

// ---------------------------------------------------------------------
extern "C" void kernel_launch(void* const* d_in, const int* in_sizes, int n_in,
                              void* d_out, int out_size) {
    const float* x  = (const float*)d_in[0];
    const void*  ei = d_in[1];
    const float* W1 = (const float*)d_in[2];
    const float* b1 = (const float*)d_in[3];
    const float* g1 = (const float*)d_in[4];
    const float* be1 = (const float*)d_in[5];
    const float* W2 = (const float*)d_in[6];
    const float* b2 = (const float*)d_in[7];
    const float* g2 = (const float*)d_in[8];
    const float* be2 = (const float*)d_in[9];
    const float* W3 = (const float*)d_in[10];
    const float* b3 = (const float*)d_in[11];
    const float* g3 = (const float*)d_in[12];
    const float* be3 = (const float*)d_in[13];
    const float* lw1 = (const float*)d_in[14];
    const float* lb1 = (const float*)d_in[15];
    const float* g4 = (const float*)d_in[16];
    const float* be4 = (const float*)d_in[17];
    const float* lw2 = (const float*)d_in[18];
    const float* lb2 = (const float*)d_in[19];
    float* out = (float*)d_out;

    const int N = NN;
    const int E = in_sizes[1] / 2;

    void* p;
    cudaGetSymbolAddress(&p, g_bufA); float* bufA = (float*)p;
    cudaGetSymbolAddress(&p, g_bufB); float* bufB = (float*)p;

    // side stream + events, created once on the (uncaptured) first call.
    static cudaStream_t s2 = nullptr;
    static cudaEvent_t ev_fork = nullptr, ev_join = nullptr;
    if (!s2) {
        cudaStreamCreateWithFlags(&s2, cudaStreamNonBlocking);
        cudaEventCreateWithFlags(&ev_fork, cudaEventDisableTiming);
        cudaEventCreateWithFlags(&ev_join, cudaEventDisableTiming);
    }

    // ---- fork: layer-1 GEMM (independent of CSR) on side stream ----
    cudaEventRecord(ev_fork, 0);
    cudaStreamWaitEvent(s2, ev_fork, 0);
    gemm_f32x2_kernel<128, 64, 8><<<(N + 127) / 128, 256, 0, s2>>>(x, W1, nullptr, bufB, N);
    cudaEventRecord(ev_join, s2);

    // ---- graph prep: CSR build on default stream (overlapped) ----
    init_detect_kernel<<<NBLK, 256>>>(ei, E, N);
    count_deg_kernel<<<(E / 4 + 255) / 256, 256>>>(ei, E);
    scan_block_sum_kernel<<<NBLK, SCAN_CHUNK>>>(N);
    scan_boff_kernel<<<1, 512>>>(NBLK);
    scan_final_kernel<<<NBLK, SCAN_CHUNK>>>(N);
    fill_csr_kernel<<<(E + 255) / 256, 256>>>(ei, E);

    // ---- join, then layer 1 aggregation ----
    cudaStreamWaitEvent(0, ev_join, 0);
    agg_ln_elu_kernel<64><<<(N * 16 + 255) / 256, 256>>>(bufB, b1, g1, be1, bufA, N);

    // ---- layer 2: agg 64-dim, then fused GEMM 64->128 + b2 + LN + ELU ----
    agg_kernel<64><<<(N * 16 + 255) / 256, 256>>>(bufA, bufB, N);
    gemm_ln_elu_kernel<64, 128, 8><<<(N + 63) / 64, 256>>>(bufB, W2, b2, g2, be2, bufA, N);

    // ---- layer 3: GEMM 128->64, then fused agg+LN+ELU+head -> out ----
    gemm_f32x2_kernel<128, 64, 8><<<(N + 127) / 128, 256>>>(bufA, W3, nullptr, bufB, N);
    agg_ln_elu_head_kernel<<<(N + 15) / 16, 256>>>(bufB, b3, g3, be3,
                                                   lw1, lb1, g4, be4, lw2, lb2,
                                                   out, N);
}